// round 2
// baseline (speedup 1.0000x reference)
#include <cuda_runtime.h>

// DRP_LAYER: 2D DRP-FDTD, 3 steps, B=2, N=2048.
// E: (B, N+1, N+1), Hx: (B, N-1, N), Hy: (B, N, N-1), all float32.
// Outputs concatenated: E2,Hx2,Hy2,E3,Hx3,Hy3,E4,Hx4,Hy4.

#define NN   2048
#define BB   2
#define CFLc 0.35f

#define ES   (NN + 1)              // 2049 — E row stride
#define HXS  (NN)                  // 2048 — Hx row stride
#define HYS  (NN - 1)              // 2047 — Hy row stride
#define ESZ  ((NN + 1) * (NN + 1))
#define HXSZ ((NN - 1) * NN)
#define HYSZ (NN * (NN - 1))

__device__ float g_coef[2];   // [0]=u = 0.25*beta - 0.1*gamma, [1]=delta

__global__ void coef_kernel(const float* __restrict__ beta,
                            const float* __restrict__ delta,
                            const float* __restrict__ gamma) {
    g_coef[0] = 0.25f * beta[0] - 0.1f * gamma[0];
    g_coef[1] = delta[0];
}

#define KF0 (-11.0f/6.0f)
#define KF1 (3.0f)
#define KF2 (-1.5f)
#define KF3 (1.0f/3.0f)
#define KB0 (-1.0f/3.0f)
#define KB1 (1.5f)
#define KB2 (-3.0f)
#define KB3 (11.0f/6.0f)

// ---------------------------------------------------------------------------
// Ampere half-step: E_out = E + CFL*(s1 - s2); output grid (N+1)x(N+1)
// j-coarsened x4: block(32,8) covers 128x8 outputs.
// ---------------------------------------------------------------------------
__global__ __launch_bounds__(256) void amper_kernel(
    const float* __restrict__ E, const float* __restrict__ Hx,
    const float* __restrict__ Hy, float* __restrict__ Eo)
{
    const int jb = blockIdx.x * 128;
    const int ib = blockIdx.y * 8;
    const int i  = ib + threadIdx.y;
    const int j0 = jb + threadIdx.x * 4;
    const int b  = blockIdx.z;

    const float* __restrict__ e  = E  + (size_t)b * ESZ;
    const float* __restrict__ hx = Hx + (size_t)b * HXSZ;
    const float* __restrict__ hy = Hy + (size_t)b * HYSZ;
    float* __restrict__ eo = Eo + (size_t)b * ESZ;

    const float u  = g_coef[0];
    const float dl = g_coef[1];
    const float c01 = u + dl - 0.5f;
    const float c11 = -2.0f * dl;
    const float c21 = dl + 0.5f - u;

#define HXv(r,c) hx[(r) * HXS + (c)]
#define HYv(r,c) hy[(r) * HYS + (c)]

    // Fast path: every output in block satisfies 5<=i<=NN-5, 5<=j<=NN-5
    const bool fast = (ib >= 8) && (ib <= NN - 16) && (jb >= 128) && (jb + 127 <= NN - 5);

    if (fast) {
        // --- s1 from Hy ---
        float A[6], Br[9], Cr[9], D[6];
#pragma unroll
        for (int t = 0; t < 6; t++) A[t]  = HYv(i-2, j0-2+t);
#pragma unroll
        for (int t = 0; t < 9; t++) Br[t] = HYv(i-1, j0-2+t);
#pragma unroll
        for (int t = 0; t < 9; t++) Cr[t] = HYv(i  , j0-5+t);
#pragma unroll
        for (int t = 0; t < 6; t++) D[t]  = HYv(i+1, j0-2+t);

        float s[4];
#pragma unroll
        for (int q = 0; q < 4; q++) {
            s[q] = -u * A[q] + u * A[q+2]
                 + c01 * Br[q] + c11 * Br[q+1] + (c21 + KF0) * Br[q+2]
                 + KF1 * Br[q+3] + KF2 * Br[q+4] + KF3 * Br[q+5]
                 + KB0 * Cr[q] + KB1 * Cr[q+1] + KB2 * Cr[q+2]
                 + (u + KB3) * Cr[q+3] - u * Cr[q+5]
                 - u * D[q] + u * D[q+2];
        }

        // --- s2 from Hx ---
        float P5[4], P4[4], P3[4], P2[7], P1[4], P0[7], Q1[4], Q2[4], Q3[4];
#pragma unroll
        for (int t = 0; t < 4; t++) P5[t] = HXv(i-5, j0+t);
#pragma unroll
        for (int t = 0; t < 4; t++) P4[t] = HXv(i-4, j0+t);
#pragma unroll
        for (int t = 0; t < 4; t++) P3[t] = HXv(i-3, j0+t);
#pragma unroll
        for (int t = 0; t < 7; t++) P2[t] = HXv(i-2, j0-2+t);
#pragma unroll
        for (int t = 0; t < 4; t++) P1[t] = HXv(i-1, j0-1+t);
#pragma unroll
        for (int t = 0; t < 7; t++) P0[t] = HXv(i  , j0-2+t);
#pragma unroll
        for (int t = 0; t < 4; t++) Q1[t] = HXv(i+1, j0-1+t);
#pragma unroll
        for (int t = 0; t < 4; t++) Q2[t] = HXv(i+2, j0-1+t);
#pragma unroll
        for (int t = 0; t < 4; t++) Q3[t] = HXv(i+3, j0-1+t);

#pragma unroll
        for (int q = 0; q < 4; q++) {
            float s2 = KB0 * P5[q] + KB1 * P4[q] + KB2 * P3[q]
                     - u * P2[q] + c01 * P2[q+1] + (u + KB3) * P2[q+2] - u * P2[q+3]
                     + c11 * P1[q]
                     + u * P0[q] + (c21 + KF0) * P0[q+1] - u * P0[q+2] + u * P0[q+3]
                     + KF1 * Q1[q] + KF2 * Q2[q] + KF3 * Q3[q];
            const int idx = i * ES + j0 + q;
            eo[idx] = e[idx] + CFLc * (s[q] - s2);
        }
        return;
    }

    // ---- generic path (edges) ----
    if (i > NN) return;
#pragma unroll
    for (int q = 0; q < 4; q++) {
        const int j = j0 + q;
        if (j > NN) break;

        const bool iin = (i >= 2) && (i <= NN - 2);
        const bool jin = (j >= 2) && (j <= NN - 2);

        float s1 = 0.0f;
        if (iin && jin) {
            s1 += -u  * HYv(i-2, j-2) + u   * HYv(i-2, j)
                + c01 * HYv(i-1, j-2) + c11 * HYv(i-1, j-1) + c21 * HYv(i-1, j)
                + u   * HYv(i  , j-2) - u   * HYv(i  , j)
                - u   * HYv(i+1, j-2) + u   * HYv(i+1, j);
        }
        if (i >= 1 && j <= NN - 5)
            s1 += KF0*HYv(i-1, j) + KF1*HYv(i-1, j+1) + KF2*HYv(i-1, j+2) + KF3*HYv(i-1, j+3);
        if (i <= NN - 1 && j >= 5)
            s1 += KB0*HYv(i, j-5) + KB1*HYv(i, j-4) + KB2*HYv(i, j-3) + KB3*HYv(i, j-2);
        if (iin && (j == 1 || j == 2))
            s1 += -HYv(i-1, j-1) + 3.0f*HYv(i-1, j) - 3.0f*HYv(i-1, j+1) + HYv(i-1, j+2);
        if (iin && (j == NN-2 || j == NN-1))
            s1 += HYv(i, j-4) - 3.0f*HYv(i, j-3) + 3.0f*HYv(i, j-2) - HYv(i, j-1);

        float s2 = 0.0f;
        if (iin && jin) {
            s2 += -u  * HXv(i-2, j-2) + c01 * HXv(i-2, j-1) + u * HXv(i-2, j) - u * HXv(i-2, j+1)
                + c11 * HXv(i-1, j-1)
                + u   * HXv(i  , j-2) + c21 * HXv(i  , j-1) - u * HXv(i  , j) + u * HXv(i  , j+1);
        }
        if (i <= NN - 5 && j >= 1)
            s2 += KF0*HXv(i, j-1) + KF1*HXv(i+1, j-1) + KF2*HXv(i+2, j-1) + KF3*HXv(i+3, j-1);
        if (i >= 5 && j <= NN - 1)
            s2 += KB0*HXv(i-5, j) + KB1*HXv(i-4, j) + KB2*HXv(i-3, j) + KB3*HXv(i-2, j);
        if ((i == 1 || i == 2) && jin)
            s2 += -HXv(i-1, j-1) + 3.0f*HXv(i, j-1) - 3.0f*HXv(i+1, j-1) + HXv(i+2, j-1);
        if ((i == NN-2 || i == NN-1) && jin)
            s2 += HXv(i-4, j) - 3.0f*HXv(i-3, j) + 3.0f*HXv(i-2, j) - HXv(i-1, j);

        const int idx = i * ES + j;
        eo[idx] = e[idx] + CFLc * (s1 - s2);
    }
#undef HXv
#undef HYv
}

// ---------------------------------------------------------------------------
// Faraday half-step: Hx_out = Hx - CFL*s3 ; Hy_out = Hy + CFL*s4
// j-coarsened x4: block(32,8) covers 128x8 output pairs.
// ---------------------------------------------------------------------------
__global__ __launch_bounds__(256) void faraday_kernel(
    const float* __restrict__ E, const float* __restrict__ Hx,
    const float* __restrict__ Hy, float* __restrict__ Hxo,
    float* __restrict__ Hyo)
{
    const int jb = blockIdx.x * 128;
    const int ib = blockIdx.y * 8;
    const int i  = ib + threadIdx.y;
    const int j0 = jb + threadIdx.x * 4;
    const int b  = blockIdx.z;

    const float* __restrict__ e  = E  + (size_t)b * ESZ;
    const float* __restrict__ hx = Hx + (size_t)b * HXSZ;
    const float* __restrict__ hy = Hy + (size_t)b * HYSZ;
    float* __restrict__ hxo = Hxo + (size_t)b * HXSZ;
    float* __restrict__ hyo = Hyo + (size_t)b * HYSZ;

    const float u  = g_coef[0];
    const float dl = g_coef[1];
    const float c01 = u + dl - 0.5f;
    const float c11 = -2.0f * dl;
    const float c21 = dl + 0.5f - u;

#define EEv(r,c) e[(r) * ES + (c)]

    // Fast path: 2<=i<=NN-4 and 2<=j, j+3<=NN-4 for all outputs in block
    const bool fast = (ib >= 8) && (ib + 7 <= NN - 4) && (jb >= 128) && (jb + 127 <= NN - 4);

    if (fast) {
        float Ew[5][8];
#pragma unroll
        for (int r = 0; r < 5; r++)
#pragma unroll
            for (int t = 0; t < 8; t++)
                Ew[r][t] = EEv(i - 1 + r, j0 - 1 + t);

#pragma unroll
        for (int q = 0; q < 4; q++) {
            float s3 = 0.5f * Ew[0][q+2]
                     - u * Ew[1][q] + c01 * Ew[1][q+1] + (u - 2.0f) * Ew[1][q+2] - u * Ew[1][q+3]
                     + (c11 - 1.5f) * Ew[2][q+1] + 1.5f * Ew[2][q+2]
                     + u * Ew[3][q] + (c21 + 2.0f) * Ew[3][q+1] - u * Ew[3][q+2] + u * Ew[3][q+3]
                     - 0.5f * Ew[4][q+1];
            hxo[i * HXS + j0 + q] = hx[i * HXS + j0 + q] - CFLc * s3;

            float s4 = -u * Ew[0][q+1] + u * Ew[0][q+3]
                     + c01 * Ew[1][q+1] + (c11 - 1.5f) * Ew[1][q+2]
                     + (c21 + 2.0f) * Ew[1][q+3] - 0.5f * Ew[1][q+4]
                     + 0.5f * Ew[2][q] + (u - 2.0f) * Ew[2][q+1] + 1.5f * Ew[2][q+2] - u * Ew[2][q+3]
                     - u * Ew[3][q+1] + u * Ew[3][q+3];
            hyo[i * HYS + j0 + q] = hy[i * HYS + j0 + q] + CFLc * s4;
        }
        return;
    }

    // ---- generic path (edges) ----
    if (i >= NN) return;
#pragma unroll
    for (int q = 0; q < 4; q++) {
        const int j = j0 + q;
        if (j >= NN) break;

        if (i <= NN - 2) {
            float s3 = 0.0f;
            if (j >= 1 && j <= NN - 2) {
                s3 += -u  * EEv(i  , j-1) + c01 * EEv(i  , j) + u * EEv(i  , j+1) - u * EEv(i  , j+2)
                    + c11 * EEv(i+1, j)
                    + u   * EEv(i+2, j-1) + c21 * EEv(i+2, j) - u * EEv(i+2, j+1) + u * EEv(i+2, j+2);
            }
            if (i <= NN - 4)
                s3 += -1.5f * EEv(i+1, j) + 2.0f * EEv(i+2, j) - 0.5f * EEv(i+3, j);
            if (i >= 2)
                s3 +=  0.5f * EEv(i-1, j+1) - 2.0f * EEv(i, j+1) + 1.5f * EEv(i+1, j+1);
            hxo[i * HXS + j] = hx[i * HXS + j] - CFLc * s3;
        }

        if (j <= NN - 2) {
            float s4 = 0.0f;
            if (i >= 1 && i <= NN - 2) {
                s4 += -u  * EEv(i-1, j) + u * EEv(i-1, j+2)
                    + c01 * EEv(i  , j) + c11 * EEv(i, j+1) + c21 * EEv(i, j+2)
                    + u   * EEv(i+1, j) - u * EEv(i+1, j+2)
                    - u   * EEv(i+2, j) + u * EEv(i+2, j+2);
            }
            if (j <= NN - 4)
                s4 += -1.5f * EEv(i, j+1) + 2.0f * EEv(i, j+2) - 0.5f * EEv(i, j+3);
            if (j >= 2)
                s4 +=  0.5f * EEv(i+1, j-1) - 2.0f * EEv(i+1, j) + 1.5f * EEv(i+1, j+1);
            hyo[i * HYS + j] = hy[i * HYS + j] + CFLc * s4;
        }
    }
#undef EEv
}

// ---------------------------------------------------------------------------
extern "C" void kernel_launch(void* const* d_in, const int* in_sizes, int n_in,
                              void* d_out, int out_size)
{
    const float* E0    = (const float*)d_in[0];
    const float* Hx0   = (const float*)d_in[1];
    const float* Hy0   = (const float*)d_in[2];
    const float* beta  = (const float*)d_in[3];
    const float* delta = (const float*)d_in[4];
    const float* gamma = (const float*)d_in[5];

    float* out = (float*)d_out;
    const size_t esz  = (size_t)BB * ESZ;
    const size_t hxsz = (size_t)BB * HXSZ;
    const size_t hysz = (size_t)BB * HYSZ;

    float* E2  = out;
    float* Hx2 = E2  + esz;
    float* Hy2 = Hx2 + hxsz;
    float* E3  = Hy2 + hysz;
    float* Hx3 = E3  + esz;
    float* Hy3 = Hx3 + hxsz;
    float* E4  = Hy3 + hysz;
    float* Hx4 = E4  + esz;
    float* Hy4 = Hx4 + hxsz;

    coef_kernel<<<1, 1>>>(beta, delta, gamma);

    dim3 blk(32, 8, 1);
    dim3 gE((NN + 1 + 127) / 128, (NN + 1 + 7) / 8, BB);   // 17 x 257 x 2
    dim3 gH((NN + 127) / 128, (NN + 7) / 8, BB);           // 16 x 256 x 2

    amper_kernel  <<<gE, blk>>>(E0, Hx0, Hy0, E2);
    faraday_kernel<<<gH, blk>>>(E2, Hx0, Hy0, Hx2, Hy2);

    amper_kernel  <<<gE, blk>>>(E2, Hx2, Hy2, E3);
    faraday_kernel<<<gH, blk>>>(E3, Hx2, Hy2, Hx3, Hy3);

    amper_kernel  <<<gE, blk>>>(E3, Hx3, Hy3, E4);
    faraday_kernel<<<gH, blk>>>(E4, Hx3, Hy3, Hx4, Hy4);
}

// round 3
// speedup vs baseline: 1.1151x; 1.1151x over previous
#include <cuda_runtime.h>

// DRP_LAYER: 2D DRP-FDTD, 3 steps, B=2, N=2048.
// E: (B, N+1, N+1), Hx: (B, N-1, N), Hy: (B, N, N-1), all float32.
// Outputs concatenated: E2,Hx2,Hy2,E3,Hx3,Hy3,E4,Hx4,Hy4.
// R3: i-direction coarsening x4, j stays warp-coalesced.

#define NN   2048
#define BB   2
#define CFLc 0.35f

#define ES   (NN + 1)
#define HXS  (NN)
#define HYS  (NN - 1)
#define ESZ  ((NN + 1) * (NN + 1))
#define HXSZ ((NN - 1) * NN)
#define HYSZ (NN * (NN - 1))

__device__ float g_coef[2];   // [0]=u = 0.25*beta - 0.1*gamma, [1]=delta

__global__ void coef_kernel(const float* __restrict__ beta,
                            const float* __restrict__ delta,
                            const float* __restrict__ gamma) {
    g_coef[0] = 0.25f * beta[0] - 0.1f * gamma[0];
    g_coef[1] = delta[0];
}

#define KF0 (-11.0f/6.0f)
#define KF1 (3.0f)
#define KF2 (-1.5f)
#define KF3 (1.0f/3.0f)
#define KB0 (-1.0f/3.0f)
#define KB1 (1.5f)
#define KB2 (-3.0f)
#define KB3 (11.0f/6.0f)

// ---------------------------------------------------------------------------
// Ampere: E_out = E + CFL*(s1 - s2); output grid (N+1)x(N+1)
// block (128,2): thread col j = jb+tx; rows i0 = ib + ty*4 .. +3.
// Block covers 128 cols x 8 rows.
// ---------------------------------------------------------------------------
__global__ __launch_bounds__(256, 2) void amper_kernel(
    const float* __restrict__ E, const float* __restrict__ Hx,
    const float* __restrict__ Hy, float* __restrict__ Eo)
{
    const int jb = blockIdx.x * 128;
    const int ib = blockIdx.y * 8;
    const int j  = jb + threadIdx.x;
    const int i0 = ib + threadIdx.y * 4;
    const int b  = blockIdx.z;

    const float* __restrict__ e  = E  + (size_t)b * ESZ;
    const float* __restrict__ hx = Hx + (size_t)b * HXSZ;
    const float* __restrict__ hy = Hy + (size_t)b * HYSZ;
    float* __restrict__ eo = Eo + (size_t)b * ESZ;

    const float u  = g_coef[0];
    const float dl = g_coef[1];
    const float c01 = u + dl - 0.5f;
    const float c11 = -2.0f * dl;
    const float c21 = dl + 0.5f - u;
    const float cKF = c21 + KF0;     // fused Hy(r-1,j) / Hx(r,j-1)
    const float cKB = u + KB3;       // fused Hy(r,j-2)  / Hx(r-2,j)

#define HXv(r,c) hx[(r) * HXS + (c)]
#define HYv(r,c) hy[(r) * HYS + (c)]

    // Fast region: all 8 block rows in [8, NN-12+7] and 128 cols in [5, NN-5]
    const bool fast = (ib >= 8) && (ib + 7 <= NN - 5) &&
                      (jb >= 128) && (jb + 127 <= NN - 5);

    if (fast) {
        float sv[4];
#pragma unroll
        for (int q = 0; q < 4; q++) {
            const int r = i0 + q;
            // s1 (from Hy): interior + KF (row r-1) + KB (row r), fused
            float s1 = -u  * HYv(r-2, j-2) + u * HYv(r-2, j)
                     + c01 * HYv(r-1, j-2) + c11 * HYv(r-1, j-1) + cKF * HYv(r-1, j)
                     + KF1 * HYv(r-1, j+1) + KF2 * HYv(r-1, j+2) + KF3 * HYv(r-1, j+3)
                     + KB0 * HYv(r, j-5) + KB1 * HYv(r, j-4) + KB2 * HYv(r, j-3)
                     + cKB * HYv(r, j-2) - u * HYv(r, j)
                     - u  * HYv(r+1, j-2) + u * HYv(r+1, j);
            // s2 (from Hx): interior + KF (col j-1) + KB (col j), fused
            float s2 = KB0 * HXv(r-5, j) + KB1 * HXv(r-4, j) + KB2 * HXv(r-3, j)
                     - u  * HXv(r-2, j-2) + c01 * HXv(r-2, j-1) + cKB * HXv(r-2, j) - u * HXv(r-2, j+1)
                     + c11 * HXv(r-1, j-1)
                     + u   * HXv(r, j-2) + cKF * HXv(r, j-1) - u * HXv(r, j) + u * HXv(r, j+1)
                     + KF1 * HXv(r+1, j-1) + KF2 * HXv(r+2, j-1) + KF3 * HXv(r+3, j-1);
            sv[q] = s1 - s2;
        }
#pragma unroll
        for (int q = 0; q < 4; q++) {
            const int idx = (i0 + q) * ES + j;
            eo[idx] = e[idx] + CFLc * sv[q];
        }
        return;
    }

    // ---- generic path (edges) ----
    if (j > NN) return;
#pragma unroll
    for (int q = 0; q < 4; q++) {
        const int i = i0 + q;
        if (i > NN) break;

        const bool iin = (i >= 2) && (i <= NN - 2);
        const bool jin = (j >= 2) && (j <= NN - 2);

        float s1 = 0.0f;
        if (iin && jin) {
            s1 += -u  * HYv(i-2, j-2) + u   * HYv(i-2, j)
                + c01 * HYv(i-1, j-2) + c11 * HYv(i-1, j-1) + c21 * HYv(i-1, j)
                + u   * HYv(i  , j-2) - u   * HYv(i  , j)
                - u   * HYv(i+1, j-2) + u   * HYv(i+1, j);
        }
        if (i >= 1 && j <= NN - 5)
            s1 += KF0*HYv(i-1, j) + KF1*HYv(i-1, j+1) + KF2*HYv(i-1, j+2) + KF3*HYv(i-1, j+3);
        if (i <= NN - 1 && j >= 5)
            s1 += KB0*HYv(i, j-5) + KB1*HYv(i, j-4) + KB2*HYv(i, j-3) + KB3*HYv(i, j-2);
        if (iin && (j == 1 || j == 2))
            s1 += -HYv(i-1, j-1) + 3.0f*HYv(i-1, j) - 3.0f*HYv(i-1, j+1) + HYv(i-1, j+2);
        if (iin && (j == NN-2 || j == NN-1))
            s1 += HYv(i, j-4) - 3.0f*HYv(i, j-3) + 3.0f*HYv(i, j-2) - HYv(i, j-1);

        float s2 = 0.0f;
        if (iin && jin) {
            s2 += -u  * HXv(i-2, j-2) + c01 * HXv(i-2, j-1) + u * HXv(i-2, j) - u * HXv(i-2, j+1)
                + c11 * HXv(i-1, j-1)
                + u   * HXv(i  , j-2) + c21 * HXv(i  , j-1) - u * HXv(i  , j) + u * HXv(i  , j+1);
        }
        if (i <= NN - 5 && j >= 1)
            s2 += KF0*HXv(i, j-1) + KF1*HXv(i+1, j-1) + KF2*HXv(i+2, j-1) + KF3*HXv(i+3, j-1);
        if (i >= 5 && j <= NN - 1)
            s2 += KB0*HXv(i-5, j) + KB1*HXv(i-4, j) + KB2*HXv(i-3, j) + KB3*HXv(i-2, j);
        if ((i == 1 || i == 2) && jin)
            s2 += -HXv(i-1, j-1) + 3.0f*HXv(i, j-1) - 3.0f*HXv(i+1, j-1) + HXv(i+2, j-1);
        if ((i == NN-2 || i == NN-1) && jin)
            s2 += HXv(i-4, j) - 3.0f*HXv(i-3, j) + 3.0f*HXv(i-2, j) - HXv(i-1, j);

        const int idx = i * ES + j;
        eo[idx] = e[idx] + CFLc * (s1 - s2);
    }
#undef HXv
#undef HYv
}

// ---------------------------------------------------------------------------
// Faraday: Hx_out = Hx - CFL*s3 ; Hy_out = Hy + CFL*s4
// Same i-coarsened x4 layout; block covers 128 cols x 8 rows.
// ---------------------------------------------------------------------------
__global__ __launch_bounds__(256, 2) void faraday_kernel(
    const float* __restrict__ E, const float* __restrict__ Hx,
    const float* __restrict__ Hy, float* __restrict__ Hxo,
    float* __restrict__ Hyo)
{
    const int jb = blockIdx.x * 128;
    const int ib = blockIdx.y * 8;
    const int j  = jb + threadIdx.x;
    const int i0 = ib + threadIdx.y * 4;
    const int b  = blockIdx.z;

    const float* __restrict__ e  = E  + (size_t)b * ESZ;
    const float* __restrict__ hx = Hx + (size_t)b * HXSZ;
    const float* __restrict__ hy = Hy + (size_t)b * HYSZ;
    float* __restrict__ hxo = Hxo + (size_t)b * HXSZ;
    float* __restrict__ hyo = Hyo + (size_t)b * HYSZ;

    const float u  = g_coef[0];
    const float dl = g_coef[1];
    const float c01 = u + dl - 0.5f;
    const float c11 = -2.0f * dl;
    const float c21 = dl + 0.5f - u;

#define EEv(r,c) e[(r) * ES + (c)]

    // Fast region: i in [2, NN-4] for all 4 rows, j in [2, NN-4]
    const bool fast = (ib >= 8) && (ib + 7 <= NN - 4) &&
                      (jb >= 128) && (jb + 127 <= NN - 4);

    if (fast) {
        float s3v[4], s4v[4];
#pragma unroll
        for (int q = 0; q < 4; q++) {
            const int i = i0 + q;
            s3v[q] = 0.5f * EEv(i-1, j+1)
                   - u * EEv(i, j-1) + c01 * EEv(i, j) + (u - 2.0f) * EEv(i, j+1) - u * EEv(i, j+2)
                   + (c11 - 1.5f) * EEv(i+1, j) + 1.5f * EEv(i+1, j+1)
                   + u * EEv(i+2, j-1) + (c21 + 2.0f) * EEv(i+2, j) - u * EEv(i+2, j+1) + u * EEv(i+2, j+2)
                   - 0.5f * EEv(i+3, j);
            s4v[q] = -u * EEv(i-1, j) + u * EEv(i-1, j+2)
                   + c01 * EEv(i, j) + (c11 - 1.5f) * EEv(i, j+1)
                   + (c21 + 2.0f) * EEv(i, j+2) - 0.5f * EEv(i, j+3)
                   + 0.5f * EEv(i+1, j-1) + (u - 2.0f) * EEv(i+1, j) + 1.5f * EEv(i+1, j+1) - u * EEv(i+1, j+2)
                   - u * EEv(i+2, j) + u * EEv(i+2, j+2);
        }
#pragma unroll
        for (int q = 0; q < 4; q++) {
            const int i = i0 + q;
            hxo[i * HXS + j] = hx[i * HXS + j] - CFLc * s3v[q];
            hyo[i * HYS + j] = hy[i * HYS + j] + CFLc * s4v[q];
        }
        return;
    }

    // ---- generic path (edges) ----
    if (j >= NN) return;
#pragma unroll
    for (int q = 0; q < 4; q++) {
        const int i = i0 + q;
        if (i >= NN) break;

        if (i <= NN - 2) {
            float s3 = 0.0f;
            if (j >= 1 && j <= NN - 2) {
                s3 += -u  * EEv(i  , j-1) + c01 * EEv(i  , j) + u * EEv(i  , j+1) - u * EEv(i  , j+2)
                    + c11 * EEv(i+1, j)
                    + u   * EEv(i+2, j-1) + c21 * EEv(i+2, j) - u * EEv(i+2, j+1) + u * EEv(i+2, j+2);
            }
            if (i <= NN - 4)
                s3 += -1.5f * EEv(i+1, j) + 2.0f * EEv(i+2, j) - 0.5f * EEv(i+3, j);
            if (i >= 2)
                s3 +=  0.5f * EEv(i-1, j+1) - 2.0f * EEv(i, j+1) + 1.5f * EEv(i+1, j+1);
            hxo[i * HXS + j] = hx[i * HXS + j] - CFLc * s3;
        }

        if (j <= NN - 2) {
            float s4 = 0.0f;
            if (i >= 1 && i <= NN - 2) {
                s4 += -u  * EEv(i-1, j) + u * EEv(i-1, j+2)
                    + c01 * EEv(i  , j) + c11 * EEv(i, j+1) + c21 * EEv(i, j+2)
                    + u   * EEv(i+1, j) - u * EEv(i+1, j+2)
                    - u   * EEv(i+2, j) + u * EEv(i+2, j+2);
            }
            if (j <= NN - 4)
                s4 += -1.5f * EEv(i, j+1) + 2.0f * EEv(i, j+2) - 0.5f * EEv(i, j+3);
            if (j >= 2)
                s4 +=  0.5f * EEv(i+1, j-1) - 2.0f * EEv(i+1, j) + 1.5f * EEv(i+1, j+1);
            hyo[i * HYS + j] = hy[i * HYS + j] + CFLc * s4;
        }
    }
#undef EEv
}

// ---------------------------------------------------------------------------
extern "C" void kernel_launch(void* const* d_in, const int* in_sizes, int n_in,
                              void* d_out, int out_size)
{
    const float* E0    = (const float*)d_in[0];
    const float* Hx0   = (const float*)d_in[1];
    const float* Hy0   = (const float*)d_in[2];
    const float* beta  = (const float*)d_in[3];
    const float* delta = (const float*)d_in[4];
    const float* gamma = (const float*)d_in[5];

    float* out = (float*)d_out;
    const size_t esz  = (size_t)BB * ESZ;
    const size_t hxsz = (size_t)BB * HXSZ;
    const size_t hysz = (size_t)BB * HYSZ;

    float* E2  = out;
    float* Hx2 = E2  + esz;
    float* Hy2 = Hx2 + hxsz;
    float* E3  = Hy2 + hysz;
    float* Hx3 = E3  + esz;
    float* Hy3 = Hx3 + hxsz;
    float* E4  = Hy3 + hysz;
    float* Hx4 = E4  + esz;
    float* Hy4 = Hx4 + hxsz;

    coef_kernel<<<1, 1>>>(beta, delta, gamma);

    dim3 blk(128, 2, 1);
    dim3 gE((NN + 1 + 127) / 128, (NN + 1 + 7) / 8, BB);   // 17 x 257 x 2
    dim3 gH((NN + 127) / 128, (NN + 7) / 8, BB);           // 16 x 256 x 2

    amper_kernel  <<<gE, blk>>>(E0, Hx0, Hy0, E2);
    faraday_kernel<<<gH, blk>>>(E2, Hx0, Hy0, Hx2, Hy2);

    amper_kernel  <<<gE, blk>>>(E2, Hx2, Hy2, E3);
    faraday_kernel<<<gH, blk>>>(E3, Hx2, Hy2, Hx3, Hy3);

    amper_kernel  <<<gE, blk>>>(E3, Hx3, Hy3, E4);
    faraday_kernel<<<gH, blk>>>(E4, Hx3, Hy3, Hx4, Hy4);
}

// round 4
// speedup vs baseline: 1.2594x; 1.1294x over previous
#include <cuda_runtime.h>

// DRP_LAYER: 2D DRP-FDTD, 3 steps, B=2, N=2048.
// R4: i-coarsening x2 (was x4), __launch_bounds__(256,3) for occupancy.

#define NN   2048
#define BB   2
#define CFLc 0.35f

#define ES   (NN + 1)
#define HXS  (NN)
#define HYS  (NN - 1)
#define ESZ  ((NN + 1) * (NN + 1))
#define HXSZ ((NN - 1) * NN)
#define HYSZ (NN * (NN - 1))

__device__ float g_coef[2];   // [0]=u = 0.25*beta - 0.1*gamma, [1]=delta

__global__ void coef_kernel(const float* __restrict__ beta,
                            const float* __restrict__ delta,
                            const float* __restrict__ gamma) {
    g_coef[0] = 0.25f * beta[0] - 0.1f * gamma[0];
    g_coef[1] = delta[0];
}

#define KF0 (-11.0f/6.0f)
#define KF1 (3.0f)
#define KF2 (-1.5f)
#define KF3 (1.0f/3.0f)
#define KB0 (-1.0f/3.0f)
#define KB1 (1.5f)
#define KB2 (-3.0f)
#define KB3 (11.0f/6.0f)

// ---------------------------------------------------------------------------
// Ampere: E_out = E + CFL*(s1 - s2); output grid (N+1)x(N+1)
// block (128,2): col j = jb+tx; rows i0 = ib + ty*2 .. +1. Block: 128 x 4.
// ---------------------------------------------------------------------------
__global__ __launch_bounds__(256, 3) void amper_kernel(
    const float* __restrict__ E, const float* __restrict__ Hx,
    const float* __restrict__ Hy, float* __restrict__ Eo)
{
    const int jb = blockIdx.x * 128;
    const int ib = blockIdx.y * 4;
    const int j  = jb + threadIdx.x;
    const int i0 = ib + threadIdx.y * 2;
    const int b  = blockIdx.z;

    const float* __restrict__ e  = E  + (size_t)b * ESZ;
    const float* __restrict__ hx = Hx + (size_t)b * HXSZ;
    const float* __restrict__ hy = Hy + (size_t)b * HYSZ;
    float* __restrict__ eo = Eo + (size_t)b * ESZ;

    const float u  = g_coef[0];
    const float dl = g_coef[1];
    const float c01 = u + dl - 0.5f;
    const float c11 = -2.0f * dl;
    const float c21 = dl + 0.5f - u;
    const float cKF = c21 + KF0;
    const float cKB = u + KB3;

#define HXv(r,c) hx[(r) * HXS + (c)]
#define HYv(r,c) hy[(r) * HYS + (c)]

    const bool fast = (ib >= 8) && (ib + 3 <= NN - 5) &&
                      (jb >= 128) && (jb + 127 <= NN - 5);

    if (fast) {
        float sv[2];
#pragma unroll
        for (int q = 0; q < 2; q++) {
            const int r = i0 + q;
            float s1 = -u  * HYv(r-2, j-2) + u * HYv(r-2, j)
                     + c01 * HYv(r-1, j-2) + c11 * HYv(r-1, j-1) + cKF * HYv(r-1, j)
                     + KF1 * HYv(r-1, j+1) + KF2 * HYv(r-1, j+2) + KF3 * HYv(r-1, j+3)
                     + KB0 * HYv(r, j-5) + KB1 * HYv(r, j-4) + KB2 * HYv(r, j-3)
                     + cKB * HYv(r, j-2) - u * HYv(r, j)
                     - u  * HYv(r+1, j-2) + u * HYv(r+1, j);
            float s2 = KB0 * HXv(r-5, j) + KB1 * HXv(r-4, j) + KB2 * HXv(r-3, j)
                     - u  * HXv(r-2, j-2) + c01 * HXv(r-2, j-1) + cKB * HXv(r-2, j) - u * HXv(r-2, j+1)
                     + c11 * HXv(r-1, j-1)
                     + u   * HXv(r, j-2) + cKF * HXv(r, j-1) - u * HXv(r, j) + u * HXv(r, j+1)
                     + KF1 * HXv(r+1, j-1) + KF2 * HXv(r+2, j-1) + KF3 * HXv(r+3, j-1);
            sv[q] = s1 - s2;
        }
#pragma unroll
        for (int q = 0; q < 2; q++) {
            const int idx = (i0 + q) * ES + j;
            eo[idx] = e[idx] + CFLc * sv[q];
        }
        return;
    }

    // ---- generic path (edges) ----
    if (j > NN) return;
#pragma unroll
    for (int q = 0; q < 2; q++) {
        const int i = i0 + q;
        if (i > NN) break;

        const bool iin = (i >= 2) && (i <= NN - 2);
        const bool jin = (j >= 2) && (j <= NN - 2);

        float s1 = 0.0f;
        if (iin && jin) {
            s1 += -u  * HYv(i-2, j-2) + u   * HYv(i-2, j)
                + c01 * HYv(i-1, j-2) + c11 * HYv(i-1, j-1) + c21 * HYv(i-1, j)
                + u   * HYv(i  , j-2) - u   * HYv(i  , j)
                - u   * HYv(i+1, j-2) + u   * HYv(i+1, j);
        }
        if (i >= 1 && j <= NN - 5)
            s1 += KF0*HYv(i-1, j) + KF1*HYv(i-1, j+1) + KF2*HYv(i-1, j+2) + KF3*HYv(i-1, j+3);
        if (i <= NN - 1 && j >= 5)
            s1 += KB0*HYv(i, j-5) + KB1*HYv(i, j-4) + KB2*HYv(i, j-3) + KB3*HYv(i, j-2);
        if (iin && (j == 1 || j == 2))
            s1 += -HYv(i-1, j-1) + 3.0f*HYv(i-1, j) - 3.0f*HYv(i-1, j+1) + HYv(i-1, j+2);
        if (iin && (j == NN-2 || j == NN-1))
            s1 += HYv(i, j-4) - 3.0f*HYv(i, j-3) + 3.0f*HYv(i, j-2) - HYv(i, j-1);

        float s2 = 0.0f;
        if (iin && jin) {
            s2 += -u  * HXv(i-2, j-2) + c01 * HXv(i-2, j-1) + u * HXv(i-2, j) - u * HXv(i-2, j+1)
                + c11 * HXv(i-1, j-1)
                + u   * HXv(i  , j-2) + c21 * HXv(i  , j-1) - u * HXv(i  , j) + u * HXv(i  , j+1);
        }
        if (i <= NN - 5 && j >= 1)
            s2 += KF0*HXv(i, j-1) + KF1*HXv(i+1, j-1) + KF2*HXv(i+2, j-1) + KF3*HXv(i+3, j-1);
        if (i >= 5 && j <= NN - 1)
            s2 += KB0*HXv(i-5, j) + KB1*HXv(i-4, j) + KB2*HXv(i-3, j) + KB3*HXv(i-2, j);
        if ((i == 1 || i == 2) && jin)
            s2 += -HXv(i-1, j-1) + 3.0f*HXv(i, j-1) - 3.0f*HXv(i+1, j-1) + HXv(i+2, j-1);
        if ((i == NN-2 || i == NN-1) && jin)
            s2 += HXv(i-4, j) - 3.0f*HXv(i-3, j) + 3.0f*HXv(i-2, j) - HXv(i-1, j);

        const int idx = i * ES + j;
        eo[idx] = e[idx] + CFLc * (s1 - s2);
    }
#undef HXv
#undef HYv
}

// ---------------------------------------------------------------------------
// Faraday: Hx_out = Hx - CFL*s3 ; Hy_out = Hy + CFL*s4
// Same x2 layout; block covers 128 cols x 4 rows.
// ---------------------------------------------------------------------------
__global__ __launch_bounds__(256, 3) void faraday_kernel(
    const float* __restrict__ E, const float* __restrict__ Hx,
    const float* __restrict__ Hy, float* __restrict__ Hxo,
    float* __restrict__ Hyo)
{
    const int jb = blockIdx.x * 128;
    const int ib = blockIdx.y * 4;
    const int j  = jb + threadIdx.x;
    const int i0 = ib + threadIdx.y * 2;
    const int b  = blockIdx.z;

    const float* __restrict__ e  = E  + (size_t)b * ESZ;
    const float* __restrict__ hx = Hx + (size_t)b * HXSZ;
    const float* __restrict__ hy = Hy + (size_t)b * HYSZ;
    float* __restrict__ hxo = Hxo + (size_t)b * HXSZ;
    float* __restrict__ hyo = Hyo + (size_t)b * HYSZ;

    const float u  = g_coef[0];
    const float dl = g_coef[1];
    const float c01 = u + dl - 0.5f;
    const float c11 = -2.0f * dl;
    const float c21 = dl + 0.5f - u;

#define EEv(r,c) e[(r) * ES + (c)]

    const bool fast = (ib >= 8) && (ib + 3 <= NN - 4) &&
                      (jb >= 128) && (jb + 127 <= NN - 4);

    if (fast) {
        float s3v[2], s4v[2];
#pragma unroll
        for (int q = 0; q < 2; q++) {
            const int i = i0 + q;
            s3v[q] = 0.5f * EEv(i-1, j+1)
                   - u * EEv(i, j-1) + c01 * EEv(i, j) + (u - 2.0f) * EEv(i, j+1) - u * EEv(i, j+2)
                   + (c11 - 1.5f) * EEv(i+1, j) + 1.5f * EEv(i+1, j+1)
                   + u * EEv(i+2, j-1) + (c21 + 2.0f) * EEv(i+2, j) - u * EEv(i+2, j+1) + u * EEv(i+2, j+2)
                   - 0.5f * EEv(i+3, j);
            s4v[q] = -u * EEv(i-1, j) + u * EEv(i-1, j+2)
                   + c01 * EEv(i, j) + (c11 - 1.5f) * EEv(i, j+1)
                   + (c21 + 2.0f) * EEv(i, j+2) - 0.5f * EEv(i, j+3)
                   + 0.5f * EEv(i+1, j-1) + (u - 2.0f) * EEv(i+1, j) + 1.5f * EEv(i+1, j+1) - u * EEv(i+1, j+2)
                   - u * EEv(i+2, j) + u * EEv(i+2, j+2);
        }
#pragma unroll
        for (int q = 0; q < 2; q++) {
            const int i = i0 + q;
            hxo[i * HXS + j] = hx[i * HXS + j] - CFLc * s3v[q];
            hyo[i * HYS + j] = hy[i * HYS + j] + CFLc * s4v[q];
        }
        return;
    }

    // ---- generic path (edges) ----
    if (j >= NN) return;
#pragma unroll
    for (int q = 0; q < 2; q++) {
        const int i = i0 + q;
        if (i >= NN) break;

        if (i <= NN - 2) {
            float s3 = 0.0f;
            if (j >= 1 && j <= NN - 2) {
                s3 += -u  * EEv(i  , j-1) + c01 * EEv(i  , j) + u * EEv(i  , j+1) - u * EEv(i  , j+2)
                    + c11 * EEv(i+1, j)
                    + u   * EEv(i+2, j-1) + c21 * EEv(i+2, j) - u * EEv(i+2, j+1) + u * EEv(i+2, j+2);
            }
            if (i <= NN - 4)
                s3 += -1.5f * EEv(i+1, j) + 2.0f * EEv(i+2, j) - 0.5f * EEv(i+3, j);
            if (i >= 2)
                s3 +=  0.5f * EEv(i-1, j+1) - 2.0f * EEv(i, j+1) + 1.5f * EEv(i+1, j+1);
            hxo[i * HXS + j] = hx[i * HXS + j] - CFLc * s3;
        }

        if (j <= NN - 2) {
            float s4 = 0.0f;
            if (i >= 1 && i <= NN - 2) {
                s4 += -u  * EEv(i-1, j) + u * EEv(i-1, j+2)
                    + c01 * EEv(i  , j) + c11 * EEv(i, j+1) + c21 * EEv(i, j+2)
                    + u   * EEv(i+1, j) - u * EEv(i+1, j+2)
                    - u   * EEv(i+2, j) + u * EEv(i+2, j+2);
            }
            if (j <= NN - 4)
                s4 += -1.5f * EEv(i, j+1) + 2.0f * EEv(i, j+2) - 0.5f * EEv(i, j+3);
            if (j >= 2)
                s4 +=  0.5f * EEv(i+1, j-1) - 2.0f * EEv(i+1, j) + 1.5f * EEv(i+1, j+1);
            hyo[i * HYS + j] = hy[i * HYS + j] + CFLc * s4;
        }
    }
#undef EEv
}

// ---------------------------------------------------------------------------
extern "C" void kernel_launch(void* const* d_in, const int* in_sizes, int n_in,
                              void* d_out, int out_size)
{
    const float* E0    = (const float*)d_in[0];
    const float* Hx0   = (const float*)d_in[1];
    const float* Hy0   = (const float*)d_in[2];
    const float* beta  = (const float*)d_in[3];
    const float* delta = (const float*)d_in[4];
    const float* gamma = (const float*)d_in[5];

    float* out = (float*)d_out;
    const size_t esz  = (size_t)BB * ESZ;
    const size_t hxsz = (size_t)BB * HXSZ;
    const size_t hysz = (size_t)BB * HYSZ;

    float* E2  = out;
    float* Hx2 = E2  + esz;
    float* Hy2 = Hx2 + hxsz;
    float* E3  = Hy2 + hysz;
    float* Hx3 = E3  + esz;
    float* Hy3 = Hx3 + hxsz;
    float* E4  = Hy3 + hysz;
    float* Hx4 = E4  + esz;
    float* Hy4 = Hx4 + hxsz;

    coef_kernel<<<1, 1>>>(beta, delta, gamma);

    dim3 blk(128, 2, 1);
    dim3 gE((NN + 1 + 127) / 128, (NN + 1 + 3) / 4, BB);   // 17 x 513 x 2
    dim3 gH((NN + 127) / 128, (NN + 3) / 4, BB);           // 16 x 512 x 2

    amper_kernel  <<<gE, blk>>>(E0, Hx0, Hy0, E2);
    faraday_kernel<<<gH, blk>>>(E2, Hx0, Hy0, Hx2, Hy2);

    amper_kernel  <<<gE, blk>>>(E2, Hx2, Hy2, E3);
    faraday_kernel<<<gH, blk>>>(E3, Hx2, Hy2, Hx3, Hy3);

    amper_kernel  <<<gE, blk>>>(E3, Hx3, Hy3, E4);
    faraday_kernel<<<gH, blk>>>(E4, Hx3, Hy3, Hx4, Hy4);
}